// round 11
// baseline (speedup 1.0000x reference)
#include <cuda_runtime.h>
#include <cuda_bf16.h>
#include <float.h>
#include <math.h>

#define LANE_WEIGHT 1.0f
#define INV_TEMP    10.0f   // 1 / 0.1

// scratch (allocation-free rule: __device__ globals)
__device__ float g_score[524288];       // per-trajectory score, NT <= 524288
__device__ float g_ce_lane[65536];      // ce_per_lane, NL <= 65536
__device__ float g_sample_loss[8192];   // per-sample loss (fallback path)
__device__ int   g_done = 0;            // last-block ticket (self-resetting)

__device__ __forceinline__ float fsqrt_approx(float x) {
    float r;
    asm("sqrt.approx.f32 %0, %1;" : "=f"(r) : "f"(x));
    return r;
}

__device__ __forceinline__
int find_sample(const int* __restrict__ cls_se, int B, int lane)
{
    int lo = 0, hi = B - 1;
    while (lo < hi) {
        int mid = (lo + hi + 1) >> 1;
        if (cls_se[2 * mid] <= lane) lo = mid; else hi = mid - 1;
    }
    return lo;
}

// ---------------------------------------------------------------------------
// Per-lane fused softmax CE (two entries per thread, warp-wide shuffles).
//   ce = tmax + log(sum exp(ts-tmax)) - (sum p*ts)/(sum p),
//   p = exp((score-smax)*INV_TEMP).
// ---------------------------------------------------------------------------
__device__ __forceinline__
float warp_lane_ce(bool actA, bool actB, float sA, float sB, float tA, float tB)
{
    float smax = fmaxf(sA, sB);
    float tmax = fmaxf(tA, tB);
    #pragma unroll
    for (int o = 16; o; o >>= 1) {
        smax = fmaxf(smax, __shfl_xor_sync(0xffffffffu, smax, o));
        tmax = fmaxf(tmax, __shfl_xor_sync(0xffffffffu, tmax, o));
    }
    float pA = actA ? expf((sA - smax) * INV_TEMP) : 0.0f;
    float pB = actB ? expf((sB - smax) * INV_TEMP) : 0.0f;
    float eA = actA ? expf(tA - tmax) : 0.0f;
    float eB = actB ? expf(tB - tmax) : 0.0f;
    float P  = pA + pB;
    float E  = eA + eB;
    float PT = (actA ? pA * tA : 0.0f) + (actB ? pB * tB : 0.0f);
    #pragma unroll
    for (int o = 16; o; o >>= 1) {
        P  += __shfl_xor_sync(0xffffffffu, P,  o);
        E  += __shfl_xor_sync(0xffffffffu, E,  o);
        PT += __shfl_xor_sync(0xffffffffu, PT, o);
    }
    return tmax + logf(E) - PT / P;
}

// ---------------------------------------------------------------------------
// Kernel A (T == 50): pure streaming ADE (UNCHANGED from the 30.6us config).
// One block per lane, one quad per trajectory, no sync, no smem.
// ---------------------------------------------------------------------------
__global__ __launch_bounds__(256)
void traj_ade_T50_kernel(const float* __restrict__ cand,   // [NT, 50, 2]
                         const float* __restrict__ gt,     // [B, 50, 2]
                         const float* __restrict__ scales, // [B]
                         const int*   __restrict__ cls_se, // [B, 2]
                         const int*   __restrict__ trj_se, // [NL, 2]
                         int B)
{
    const int lane = blockIdx.x;
    const int tid  = threadIdx.x;

    const int ts_start = trj_se[2 * lane];
    const int ts_end   = trj_se[2 * lane + 1];
    int cnt = ts_end - ts_start;
    if (cnt > 64) cnt = 64;

    const int sample = find_sample(cls_se, B, lane);
    const float inv_scale = 1.0f / scales[sample];

    const int tl  = tid >> 2;          // trajectory within lane (0..63)
    const int sub = tid & 3;

    float acc0 = 0.0f, acc1 = 0.0f;
    if (tl < cnt) {
        const float4* base = reinterpret_cast<const float4*>(cand)
                             + (size_t)(ts_start + tl) * 25;
        const float2* gt2 = reinterpret_cast<const float2*>(gt) + sample * 50;
        #pragma unroll
        for (int j = 0; j < 7; j++) {
            const int r = sub + 4 * j;
            if (r < 25) {
                float4 v  = base[r];
                float2 g0 = __ldg(&gt2[2 * r]);
                float2 g1 = __ldg(&gt2[2 * r + 1]);
                float dx0 = v.x - g0.x, dy0 = v.y - g0.y;
                float dx1 = v.z - g1.x, dy1 = v.w - g1.y;
                acc0 += fsqrt_approx(fmaf(dx0, dx0, fmaf(dy0, dy0, 1e-12f)));
                acc1 += fsqrt_approx(fmaf(dx1, dx1, fmaf(dy1, dy1, 1e-12f)));
            }
        }
    }
    float acc = acc0 + acc1;
    acc += __shfl_xor_sync(0xffffffffu, acc, 1);
    acc += __shfl_xor_sync(0xffffffffu, acc, 2);

    if (sub == 0 && tl < cnt)
        g_score[ts_start + tl] = -(acc * 0.02f) * inv_scale;
}

// ---------------------------------------------------------------------------
// Kernel B: warp-per-lane CE (8 lanes / 256-thr block) + last-block ticket.
// Last block alone runs the whole sample-level pass (thread-per-sample,
// fixed-order deterministic) and writes the final mean.
// ---------------------------------------------------------------------------
__global__ __launch_bounds__(256)
void lane_ce_final_kernel(const float* __restrict__ traj_scores, // [NT]
                          const float* __restrict__ lane_scores, // [NL]
                          const int*   __restrict__ oracle,      // [NL]
                          const int*   __restrict__ cls_se,      // [B, 2]
                          const int*   __restrict__ trj_se,      // [NL, 2]
                          float* __restrict__ out, int NL, int B)
{
    const int tid = threadIdx.x;
    const int wid = tid >> 5;
    const int lid = tid & 31;
    const int lane = blockIdx.x * 8 + wid;

    if (lane < NL) {
        const int ts_start = trj_se[2 * lane];
        const int ts_end   = trj_se[2 * lane + 1];
        int cnt = ts_end - ts_start;
        if (cnt > 64) cnt = 64;

        const bool actA = (lid < cnt);
        const bool actB = (lid + 32 < cnt);
        float sA = actA ? g_score[ts_start + lid]          : -FLT_MAX;
        float sB = actB ? g_score[ts_start + lid + 32]     : -FLT_MAX;
        float tA = actA ? traj_scores[ts_start + lid]      : -FLT_MAX;
        float tB = actB ? traj_scores[ts_start + lid + 32] : -FLT_MAX;

        float ce = warp_lane_ce(actA, actB, sA, sB, tA, tB);
        if (lid == 0) g_ce_lane[lane] = ce;
    }

    // ---- last-block-done ticket ----
    __threadfence();
    __syncthreads();
    __shared__ bool s_last;
    if (tid == 0) {
        int t = atomicAdd(&g_done, 1);
        s_last = (t == gridDim.x - 1);
    }
    __syncthreads();
    if (!s_last) return;

    __threadfence();   // all g_ce_lane writes visible

    // ---- sample-level pass: thread t handles samples t, t+256, ... ----
    float acc = 0.0f;
    for (int b = tid; b < B; b += 256) {
        const int s = cls_se[2 * b];
        const int e = cls_se[2 * b + 1];
        int nl = e - s;
        if (nl > 32) nl = 32;

        float m = -FLT_MAX;
        for (int li = 0; li < nl; li++)
            m = fmaxf(m, lane_scores[s + li]);

        float Z = 0.0f, OC = 0.0f, CE = 0.0f, LLc = 0.0f;
        for (int li = 0; li < nl; li++) {
            float ls = lane_scores[s + li];   // L1-hit (2nd touch)
            Z += expf(ls - m);
            if (oracle[s + li] != 0) {
                OC  += 1.0f;
                CE  += g_ce_lane[s + li];
                LLc += (m - ls);
            }
        }
        const float lse = logf(Z);
        // sum over oracle lanes of (m + lse - ls) = OC*lse + LLc
        float lane_loss = ((LLc + OC * lse) / OC) * LANE_WEIGHT;
        acc += lane_loss + CE / OC;
    }

    // deterministic block reduction (fixed tree)
    __shared__ float red[8];
    #pragma unroll
    for (int o = 16; o; o >>= 1) acc += __shfl_xor_sync(0xffffffffu, acc, o);
    if (lid == 0) red[wid] = acc;
    __syncthreads();
    if (wid == 0) {
        float a = (lid < 8) ? red[lid] : 0.0f;
        #pragma unroll
        for (int o = 4; o; o >>= 1) a += __shfl_xor_sync(0xffffffffu, a, o);
        if (lid == 0) {
            out[0] = a / (float)B;
            *((volatile int*)&g_done) = 0;   // reset for next graph replay
        }
    }
}

// ---------------------------------------------------------------------------
// Generic fallback (any T): block-per-lane ADE + in-block epilogue.
// ---------------------------------------------------------------------------
__global__ __launch_bounds__(256)
void traj_ce_kernel(const float* __restrict__ traj_scores,
                    const float* __restrict__ cand,
                    const float* __restrict__ gt,
                    const float* __restrict__ scales,
                    const int*   __restrict__ cls_se,
                    const int*   __restrict__ trj_se,
                    int B, int T)
{
    const int lane = blockIdx.x;
    const int tid  = threadIdx.x;

    const int ts_start = trj_se[2 * lane];
    const int ts_end   = trj_se[2 * lane + 1];
    int cnt = ts_end - ts_start;
    if (cnt > 64) cnt = 64;

    const int sample = find_sample(cls_se, B, lane);

    __shared__ __align__(8) float s_gt[1024];
    __shared__ float s_score[64], s_ts[64];

    const int t2 = T * 2;
    for (int i = tid; i < t2 && i < 1024; i += blockDim.x)
        s_gt[i] = gt[(size_t)sample * t2 + i];
    __syncthreads();

    const float inv_scale = 1.0f / scales[sample];

    const int q   = tid >> 2;
    const int sub = tid & 3;
    float acc = 0.0f;
    if (q < cnt) {
        const float2* base = reinterpret_cast<const float2*>(cand)
                             + (size_t)(ts_start + q) * T;
        const float2* g2 = reinterpret_cast<const float2*>(s_gt);
        #pragma unroll 4
        for (int t = sub; t < T; t += 4) {
            float2 c = base[t];
            float2 g = g2[t];
            float dx = c.x - g.x;
            float dy = c.y - g.y;
            acc += fsqrt_approx(fmaf(dx, dx, fmaf(dy, dy, 1e-12f)));
        }
    }
    acc += __shfl_xor_sync(0xffffffffu, acc, 1);
    acc += __shfl_xor_sync(0xffffffffu, acc, 2);

    if (sub == 0 && q < cnt) {
        float ade = acc / (float)T;
        s_score[q] = -ade * inv_scale;
        s_ts[q]    = traj_scores[ts_start + q];
    }
    __syncthreads();

    if (tid >= 32) return;
    const bool actA = (tid < cnt);
    const bool actB = (tid + 32 < cnt);
    float sA = actA ? s_score[tid]      : -FLT_MAX;
    float sB = actB ? s_score[tid + 32] : -FLT_MAX;
    float tA = actA ? s_ts[tid]         : -FLT_MAX;
    float tB = actB ? s_ts[tid + 32]    : -FLT_MAX;
    float ce = warp_lane_ce(actA, actB, sA, sB, tA, tB);
    if (tid == 0) g_ce_lane[lane] = ce;
}

__global__ __launch_bounds__(32)
void sample_loss_kernel(const float* __restrict__ lane_scores,
                        const int*   __restrict__ oracle,
                        const int*   __restrict__ cls_se)
{
    const int b = blockIdx.x;
    const int i = threadIdx.x;
    const int s = cls_se[2 * b];
    const int e = cls_se[2 * b + 1];
    int cnt = e - s;
    if (cnt > 32) cnt = 32;

    const bool act = (i < cnt);
    float ls  = act ? lane_scores[s + i] : -FLT_MAX;
    bool  orc = act && (oracle[s + i] != 0);
    float ce  = orc ? g_ce_lane[s + i] : 0.0f;

    float m = ls;
    #pragma unroll
    for (int o = 16; o; o >>= 1) m = fmaxf(m, __shfl_xor_sync(0xffffffffu, m, o));

    float ev = act ? expf(ls - m) : 0.0f;
    float oc = orc ? 1.0f : 0.0f;
    float Z = ev, OC = oc, CE = ce;
    #pragma unroll
    for (int o = 16; o; o >>= 1) {
        Z  += __shfl_xor_sync(0xffffffffu, Z, o);
        OC += __shfl_xor_sync(0xffffffffu, OC, o);
        CE += __shfl_xor_sync(0xffffffffu, CE, o);
    }
    const float lse = logf(Z);
    float llc = orc ? (m + lse - ls) : 0.0f;
    float LL = llc;
    #pragma unroll
    for (int o = 16; o; o >>= 1) LL += __shfl_xor_sync(0xffffffffu, LL, o);

    if (i == 0)
        g_sample_loss[b] = (LL / OC) * LANE_WEIGHT + CE / OC;
}

__global__ __launch_bounds__(256)
void final_mean_kernel(float* __restrict__ out, int B)
{
    __shared__ float red[256];
    const int tid = threadIdx.x;
    float v = 0.0f;
    for (int i = tid; i < B; i += 256) v += g_sample_loss[i];
    red[tid] = v;
    __syncthreads();
    for (int o = 128; o >= 32; o >>= 1) {
        if (tid < o) red[tid] += red[tid + o];
        __syncthreads();
    }
    if (tid < 32) {
        float a = red[tid];
        #pragma unroll
        for (int o = 16; o; o >>= 1) a += __shfl_xor_sync(0xffffffffu, a, o);
        if (tid == 0) out[0] = a / (float)B;
    }
}

// ---------------------------------------------------------------------------
extern "C" void kernel_launch(void* const* d_in, const int* in_sizes, int n_in,
                              void* d_out, int out_size)
{
    const float* lane_scores = (const float*)d_in[0];   // [NL]
    const float* traj_scores = (const float*)d_in[1];   // [NT, 1]
    const float* cand        = (const float*)d_in[2];   // [NT, T, 2]
    const float* gt          = (const float*)d_in[3];   // [B, T, 2]
    const float* scales      = (const float*)d_in[4];   // [B]
    const int*   oracle      = (const int*)  d_in[5];   // [NL]
    const int*   cls_se      = (const int*)  d_in[6];   // [B, 2]
    const int*   trj_se      = (const int*)  d_in[7];   // [NL, 2]

    const int NL = in_sizes[0];
    const int NT = in_sizes[1];
    const int B  = in_sizes[6] / 2;
    const int T  = in_sizes[3] / (2 * B);

    if (T == 50 && NT <= 524288 && NL <= 65536 && B <= 8192) {
        traj_ade_T50_kernel<<<NL, 256>>>(cand, gt, scales, cls_se, trj_se, B);
        lane_ce_final_kernel<<<(NL + 7) / 8, 256>>>(traj_scores, lane_scores,
                                                    oracle, cls_se, trj_se,
                                                    (float*)d_out, NL, B);
    } else {
        traj_ce_kernel<<<NL, 256>>>(traj_scores, cand, gt, scales,
                                    cls_se, trj_se, B, T);
        sample_loss_kernel<<<B, 32>>>(lane_scores, oracle, cls_se);
        final_mean_kernel<<<1, 256>>>((float*)d_out, B);
    }
}

// round 12
// speedup vs baseline: 1.1393x; 1.1393x over previous
#include <cuda_runtime.h>
#include <cuda_bf16.h>
#include <float.h>
#include <math.h>

#define LANE_WEIGHT 1.0f
#define INV_TEMP    10.0f   // 1 / 0.1

// scratch (allocation-free rule: __device__ globals)
__device__ float g_score[524288];       // per-trajectory score, NT <= 524288
__device__ float g_ce_lane[65536];      // ce_per_lane (fallback path)
__device__ float g_sample_loss[8192];   // per-sample loss, B <= 8192
__device__ int   g_done = 0;            // last-block ticket (self-resetting)

__device__ __forceinline__ float fsqrt_approx(float x) {
    float r;
    asm("sqrt.approx.f32 %0, %1;" : "=f"(r) : "f"(x));
    return r;
}

__device__ __forceinline__
int find_sample(const int* __restrict__ cls_se, int B, int lane)
{
    int lo = 0, hi = B - 1;
    while (lo < hi) {
        int mid = (lo + hi + 1) >> 1;
        if (cls_se[2 * mid] <= lane) lo = mid; else hi = mid - 1;
    }
    return lo;
}

// ---------------------------------------------------------------------------
// Per-lane fused softmax CE (two entries per thread, warp-wide shuffles).
// ---------------------------------------------------------------------------
__device__ __forceinline__
float warp_lane_ce(bool actA, bool actB, float sA, float sB, float tA, float tB)
{
    float smax = fmaxf(sA, sB);
    float tmax = fmaxf(tA, tB);
    #pragma unroll
    for (int o = 16; o; o >>= 1) {
        smax = fmaxf(smax, __shfl_xor_sync(0xffffffffu, smax, o));
        tmax = fmaxf(tmax, __shfl_xor_sync(0xffffffffu, tmax, o));
    }
    float pA = actA ? expf((sA - smax) * INV_TEMP) : 0.0f;
    float pB = actB ? expf((sB - smax) * INV_TEMP) : 0.0f;
    float eA = actA ? expf(tA - tmax) : 0.0f;
    float eB = actB ? expf(tB - tmax) : 0.0f;
    float P  = pA + pB;
    float E  = eA + eB;
    float PT = (actA ? pA * tA : 0.0f) + (actB ? pB * tB : 0.0f);
    #pragma unroll
    for (int o = 16; o; o >>= 1) {
        P  += __shfl_xor_sync(0xffffffffu, P,  o);
        E  += __shfl_xor_sync(0xffffffffu, E,  o);
        PT += __shfl_xor_sync(0xffffffffu, PT, o);
    }
    return tmax + logf(E) - PT / P;
}

// ---------------------------------------------------------------------------
// Kernel A (T == 50): streaming ADE with FRONT-BATCHED candidate loads.
//   1. load trj_se, issue all 7 LDG.128 for this thread's trajectory slice
//   2. while those are in flight: binary-search sample, load scales, gt
//   3. compute distances, quad-reduce, write g_score
// No __syncthreads, no shared memory.
// ---------------------------------------------------------------------------
__global__ __launch_bounds__(256)
void traj_ade_T50_kernel(const float* __restrict__ cand,   // [NT, 50, 2]
                         const float* __restrict__ gt,     // [B, 50, 2]
                         const float* __restrict__ scales, // [B]
                         const int*   __restrict__ cls_se, // [B, 2]
                         const int*   __restrict__ trj_se, // [NL, 2]
                         int B)
{
    const int lane = blockIdx.x;
    const int tid  = threadIdx.x;

    const int ts_start = trj_se[2 * lane];
    const int ts_end   = trj_se[2 * lane + 1];
    int cnt = ts_end - ts_start;
    if (cnt > 64) cnt = 64;

    const int tl  = tid >> 2;          // trajectory within lane (0..63)
    const int sub = tid & 3;
    const bool act = (tl < cnt);

    // ---- 1. front-batched candidate loads (up to 7 independent LDG.128) ----
    float4 v[7];
    const float4* base = reinterpret_cast<const float4*>(cand)
                         + (size_t)(ts_start + tl) * 25;
    #pragma unroll
    for (int j = 0; j < 7; j++) {
        const int r = sub + 4 * j;
        if (act && r < 25) v[j] = base[r];
    }

    // ---- 2. index math overlapping the in-flight loads ----
    const int sample = find_sample(cls_se, B, lane);
    const float inv_scale = 1.0f / scales[sample];
    const float2* gt2 = reinterpret_cast<const float2*>(gt) + sample * 50;

    // ---- 3. compute ----
    float acc0 = 0.0f, acc1 = 0.0f;
    #pragma unroll
    for (int j = 0; j < 7; j++) {
        const int r = sub + 4 * j;
        if (act && r < 25) {
            float2 g0 = __ldg(&gt2[2 * r]);
            float2 g1 = __ldg(&gt2[2 * r + 1]);
            float dx0 = v[j].x - g0.x, dy0 = v[j].y - g0.y;
            float dx1 = v[j].z - g1.x, dy1 = v[j].w - g1.y;
            acc0 += fsqrt_approx(fmaf(dx0, dx0, fmaf(dy0, dy0, 1e-12f)));
            acc1 += fsqrt_approx(fmaf(dx1, dx1, fmaf(dy1, dy1, 1e-12f)));
        }
    }
    float acc = acc0 + acc1;
    acc += __shfl_xor_sync(0xffffffffu, acc, 1);
    acc += __shfl_xor_sync(0xffffffffu, acc, 2);

    if (sub == 0 && act)
        g_score[ts_start + tl] = -(acc * 0.02f) * inv_scale;
}

// ---------------------------------------------------------------------------
// Kernel B (fused tail, UNCHANGED from the 30.6us R9 config):
// one block per sample, 512 threads = 16 warps.
// ---------------------------------------------------------------------------
__global__ __launch_bounds__(512)
void sample_fused_kernel(const float* __restrict__ traj_scores, // [NT]
                         const float* __restrict__ lane_scores, // [NL]
                         const int*   __restrict__ oracle,      // [NL]
                         const int*   __restrict__ cls_se,      // [B, 2]
                         const int*   __restrict__ trj_se,      // [NL, 2]
                         float* __restrict__ out, int B)
{
    const int b   = blockIdx.x;
    const int tid = threadIdx.x;
    const int wid = tid >> 5;
    const int lid = tid & 31;

    const int s = cls_se[2 * b];
    const int e = cls_se[2 * b + 1];
    int nlanes = e - s;
    if (nlanes > 32) nlanes = 32;

    __shared__ float s_ce[32];
    __shared__ bool  s_last;

    #pragma unroll
    for (int pass = 0; pass < 2; pass++) {
        const int li = wid + 16 * pass;
        if (li < nlanes) {
            const int lane = s + li;
            const int ts_start = trj_se[2 * lane];
            const int ts_end   = trj_se[2 * lane + 1];
            int cnt = ts_end - ts_start;
            if (cnt > 64) cnt = 64;

            const bool actA = (lid < cnt);
            const bool actB = (lid + 32 < cnt);
            float sA = actA ? g_score[ts_start + lid]          : -FLT_MAX;
            float sB = actB ? g_score[ts_start + lid + 32]     : -FLT_MAX;
            float tA = actA ? traj_scores[ts_start + lid]      : -FLT_MAX;
            float tB = actB ? traj_scores[ts_start + lid + 32] : -FLT_MAX;

            float ce = warp_lane_ce(actA, actB, sA, sB, tA, tB);
            if (lid == 0) s_ce[li] = ce;
        }
    }
    __syncthreads();

    if (wid == 0) {
        const bool act = (lid < nlanes);
        float ls  = act ? lane_scores[s + lid] : -FLT_MAX;
        bool  orc = act && (oracle[s + lid] != 0);
        float ce  = orc ? s_ce[lid] : 0.0f;

        float m = ls;
        #pragma unroll
        for (int o = 16; o; o >>= 1)
            m = fmaxf(m, __shfl_xor_sync(0xffffffffu, m, o));

        float ev = act ? expf(ls - m) : 0.0f;
        float oc = orc ? 1.0f : 0.0f;
        float Z = ev, OC = oc, CE = ce;
        #pragma unroll
        for (int o = 16; o; o >>= 1) {
            Z  += __shfl_xor_sync(0xffffffffu, Z, o);
            OC += __shfl_xor_sync(0xffffffffu, OC, o);
            CE += __shfl_xor_sync(0xffffffffu, CE, o);
        }
        const float lse = logf(Z);
        float llc = orc ? (m + lse - ls) : 0.0f;
        float LL = llc;
        #pragma unroll
        for (int o = 16; o; o >>= 1)
            LL += __shfl_xor_sync(0xffffffffu, LL, o);

        if (lid == 0)
            g_sample_loss[b] = (LL / OC) * LANE_WEIGHT + CE / OC;
    }

    // ---- last-block-done: deterministic final mean ----
    __threadfence();
    __syncthreads();
    if (tid == 0) {
        int t = atomicAdd(&g_done, 1);
        s_last = (t == gridDim.x - 1);
    }
    __syncthreads();
    if (!s_last) return;

    __threadfence();
    __shared__ float red[16];
    float v = 0.0f;
    for (int i = tid; i < B; i += 512) v += g_sample_loss[i];
    #pragma unroll
    for (int o = 16; o; o >>= 1) v += __shfl_xor_sync(0xffffffffu, v, o);
    if (lid == 0) red[wid] = v;
    __syncthreads();
    if (wid == 0) {
        float a = (lid < 16) ? red[lid] : 0.0f;
        #pragma unroll
        for (int o = 8; o; o >>= 1) a += __shfl_xor_sync(0xffffffffu, a, o);
        if (lid == 0) {
            out[0] = a / (float)B;
            *((volatile int*)&g_done) = 0;   // reset for next graph replay
        }
    }
}

// ---------------------------------------------------------------------------
// Generic fallback (any T): block-per-lane ADE + in-block epilogue.
// ---------------------------------------------------------------------------
__global__ __launch_bounds__(256)
void traj_ce_kernel(const float* __restrict__ traj_scores,
                    const float* __restrict__ cand,
                    const float* __restrict__ gt,
                    const float* __restrict__ scales,
                    const int*   __restrict__ cls_se,
                    const int*   __restrict__ trj_se,
                    int B, int T)
{
    const int lane = blockIdx.x;
    const int tid  = threadIdx.x;

    const int ts_start = trj_se[2 * lane];
    const int ts_end   = trj_se[2 * lane + 1];
    int cnt = ts_end - ts_start;
    if (cnt > 64) cnt = 64;

    const int sample = find_sample(cls_se, B, lane);

    __shared__ __align__(8) float s_gt[1024];
    __shared__ float s_score[64], s_ts[64];

    const int t2 = T * 2;
    for (int i = tid; i < t2 && i < 1024; i += blockDim.x)
        s_gt[i] = gt[(size_t)sample * t2 + i];
    __syncthreads();

    const float inv_scale = 1.0f / scales[sample];

    const int q   = tid >> 2;
    const int sub = tid & 3;
    float acc = 0.0f;
    if (q < cnt) {
        const float2* base = reinterpret_cast<const float2*>(cand)
                             + (size_t)(ts_start + q) * T;
        const float2* g2 = reinterpret_cast<const float2*>(s_gt);
        #pragma unroll 4
        for (int t = sub; t < T; t += 4) {
            float2 c = base[t];
            float2 g = g2[t];
            float dx = c.x - g.x;
            float dy = c.y - g.y;
            acc += fsqrt_approx(fmaf(dx, dx, fmaf(dy, dy, 1e-12f)));
        }
    }
    acc += __shfl_xor_sync(0xffffffffu, acc, 1);
    acc += __shfl_xor_sync(0xffffffffu, acc, 2);

    if (sub == 0 && q < cnt) {
        float ade = acc / (float)T;
        s_score[q] = -ade * inv_scale;
        s_ts[q]    = traj_scores[ts_start + q];
    }
    __syncthreads();

    if (tid >= 32) return;
    const bool actA = (tid < cnt);
    const bool actB = (tid + 32 < cnt);
    float sA = actA ? s_score[tid]      : -FLT_MAX;
    float sB = actB ? s_score[tid + 32] : -FLT_MAX;
    float tA = actA ? s_ts[tid]         : -FLT_MAX;
    float tB = actB ? s_ts[tid + 32]    : -FLT_MAX;
    float ce = warp_lane_ce(actA, actB, sA, sB, tA, tB);
    if (tid == 0) g_ce_lane[lane] = ce;
}

__global__ __launch_bounds__(32)
void sample_loss_kernel(const float* __restrict__ lane_scores,
                        const int*   __restrict__ oracle,
                        const int*   __restrict__ cls_se)
{
    const int b = blockIdx.x;
    const int i = threadIdx.x;
    const int s = cls_se[2 * b];
    const int e = cls_se[2 * b + 1];
    int cnt = e - s;
    if (cnt > 32) cnt = 32;

    const bool act = (i < cnt);
    float ls  = act ? lane_scores[s + i] : -FLT_MAX;
    bool  orc = act && (oracle[s + i] != 0);
    float ce  = orc ? g_ce_lane[s + i] : 0.0f;

    float m = ls;
    #pragma unroll
    for (int o = 16; o; o >>= 1) m = fmaxf(m, __shfl_xor_sync(0xffffffffu, m, o));

    float ev = act ? expf(ls - m) : 0.0f;
    float oc = orc ? 1.0f : 0.0f;
    float Z = ev, OC = oc, CE = ce;
    #pragma unroll
    for (int o = 16; o; o >>= 1) {
        Z  += __shfl_xor_sync(0xffffffffu, Z, o);
        OC += __shfl_xor_sync(0xffffffffu, OC, o);
        CE += __shfl_xor_sync(0xffffffffu, CE, o);
    }
    const float lse = logf(Z);
    float llc = orc ? (m + lse - ls) : 0.0f;
    float LL = llc;
    #pragma unroll
    for (int o = 16; o; o >>= 1) LL += __shfl_xor_sync(0xffffffffu, LL, o);

    if (i == 0)
        g_sample_loss[b] = (LL / OC) * LANE_WEIGHT + CE / OC;
}

__global__ __launch_bounds__(256)
void final_mean_kernel(float* __restrict__ out, int B)
{
    __shared__ float red[256];
    const int tid = threadIdx.x;
    float v = 0.0f;
    for (int i = tid; i < B; i += 256) v += g_sample_loss[i];
    red[tid] = v;
    __syncthreads();
    for (int o = 128; o >= 32; o >>= 1) {
        if (tid < o) red[tid] += red[tid + o];
        __syncthreads();
    }
    if (tid < 32) {
        float a = red[tid];
        #pragma unroll
        for (int o = 16; o; o >>= 1) a += __shfl_xor_sync(0xffffffffu, a, o);
        if (tid == 0) out[0] = a / (float)B;
    }
}

// ---------------------------------------------------------------------------
extern "C" void kernel_launch(void* const* d_in, const int* in_sizes, int n_in,
                              void* d_out, int out_size)
{
    const float* lane_scores = (const float*)d_in[0];   // [NL]
    const float* traj_scores = (const float*)d_in[1];   // [NT, 1]
    const float* cand        = (const float*)d_in[2];   // [NT, T, 2]
    const float* gt          = (const float*)d_in[3];   // [B, T, 2]
    const float* scales      = (const float*)d_in[4];   // [B]
    const int*   oracle      = (const int*)  d_in[5];   // [NL]
    const int*   cls_se      = (const int*)  d_in[6];   // [B, 2]
    const int*   trj_se      = (const int*)  d_in[7];   // [NL, 2]

    const int NL = in_sizes[0];
    const int NT = in_sizes[1];
    const int B  = in_sizes[6] / 2;
    const int T  = in_sizes[3] / (2 * B);

    if (T == 50 && NT <= 524288 && B <= 8192) {
        traj_ade_T50_kernel<<<NL, 256>>>(cand, gt, scales, cls_se, trj_se, B);
        sample_fused_kernel<<<B, 512>>>(traj_scores, lane_scores, oracle,
                                        cls_se, trj_se, (float*)d_out, B);
    } else {
        traj_ce_kernel<<<NL, 256>>>(traj_scores, cand, gt, scales,
                                    cls_se, trj_se, B, T);
        sample_loss_kernel<<<B, 32>>>(lane_scores, oracle, cls_se);
        final_mean_kernel<<<1, 256>>>((float*)d_out, B);
    }
}

// round 15
// speedup vs baseline: 1.2095x; 1.0617x over previous
#include <cuda_runtime.h>
#include <cuda_bf16.h>
#include <float.h>
#include <math.h>

#define LANE_WEIGHT 1.0f
#define INV_TEMP    10.0f   // 1 / 0.1

// scratch (allocation-free rule: __device__ globals)
__device__ float g_score[524288];       // per-trajectory score, NT <= 524288
__device__ float g_ce_lane[65536];      // ce_per_lane (fallback path)
__device__ float g_sample_loss[8192];   // per-sample loss, B <= 8192
__device__ int   g_done = 0;            // last-block ticket (self-resetting)

__device__ __forceinline__ float fsqrt_approx(float x) {
    float r;
    asm("sqrt.approx.f32 %0, %1;" : "=f"(r) : "f"(x));
    return r;
}

__device__ __forceinline__
int find_sample(const int* __restrict__ cls_se, int B, int lane)
{
    int lo = 0, hi = B - 1;
    while (lo < hi) {
        int mid = (lo + hi + 1) >> 1;
        if (cls_se[2 * mid] <= lane) lo = mid; else hi = mid - 1;
    }
    return lo;
}

// ---------------------------------------------------------------------------
// Per-lane fused softmax CE (two entries per thread, warp-wide shuffles).
// ---------------------------------------------------------------------------
__device__ __forceinline__
float warp_lane_ce(bool actA, bool actB, float sA, float sB, float tA, float tB)
{
    float smax = fmaxf(sA, sB);
    float tmax = fmaxf(tA, tB);
    #pragma unroll
    for (int o = 16; o; o >>= 1) {
        smax = fmaxf(smax, __shfl_xor_sync(0xffffffffu, smax, o));
        tmax = fmaxf(tmax, __shfl_xor_sync(0xffffffffu, tmax, o));
    }
    float pA = actA ? expf((sA - smax) * INV_TEMP) : 0.0f;
    float pB = actB ? expf((sB - smax) * INV_TEMP) : 0.0f;
    float eA = actA ? expf(tA - tmax) : 0.0f;
    float eB = actB ? expf(tB - tmax) : 0.0f;
    float P  = pA + pB;
    float E  = eA + eB;
    float PT = (actA ? pA * tA : 0.0f) + (actB ? pB * tB : 0.0f);
    #pragma unroll
    for (int o = 16; o; o >>= 1) {
        P  += __shfl_xor_sync(0xffffffffu, P,  o);
        E  += __shfl_xor_sync(0xffffffffu, E,  o);
        PT += __shfl_xor_sync(0xffffffffu, PT, o);
    }
    return tmax + logf(E) - PT / P;
}

// ---------------------------------------------------------------------------
// Kernel A (T == 50): streaming ADE with front-batched candidate loads.
// Triggers dependent launch (PDL) after its g_score store.
// ---------------------------------------------------------------------------
__global__ __launch_bounds__(256)
void traj_ade_T50_kernel(const float* __restrict__ cand,   // [NT, 50, 2]
                         const float* __restrict__ gt,     // [B, 50, 2]
                         const float* __restrict__ scales, // [B]
                         const int*   __restrict__ cls_se, // [B, 2]
                         const int*   __restrict__ trj_se, // [NL, 2]
                         int B)
{
    const int lane = blockIdx.x;
    const int tid  = threadIdx.x;

    const int ts_start = trj_se[2 * lane];
    const int ts_end   = trj_se[2 * lane + 1];
    int cnt = ts_end - ts_start;
    if (cnt > 64) cnt = 64;

    const int tl  = tid >> 2;          // trajectory within lane (0..63)
    const int sub = tid & 3;
    const bool act = (tl < cnt);

    // ---- 1. front-batched candidate loads (up to 7 independent LDG.128) ----
    float4 v[7];
    const float4* base = reinterpret_cast<const float4*>(cand)
                         + (size_t)(ts_start + tl) * 25;
    #pragma unroll
    for (int j = 0; j < 7; j++) {
        const int r = sub + 4 * j;
        if (act && r < 25) v[j] = base[r];
    }

    // ---- 2. index math overlapping the in-flight loads ----
    const int sample = find_sample(cls_se, B, lane);
    const float inv_scale = 1.0f / scales[sample];
    const float2* gt2 = reinterpret_cast<const float2*>(gt) + sample * 50;

    // ---- 3. compute ----
    float acc0 = 0.0f, acc1 = 0.0f;
    #pragma unroll
    for (int j = 0; j < 7; j++) {
        const int r = sub + 4 * j;
        if (act && r < 25) {
            float2 g0 = __ldg(&gt2[2 * r]);
            float2 g1 = __ldg(&gt2[2 * r + 1]);
            float dx0 = v[j].x - g0.x, dy0 = v[j].y - g0.y;
            float dx1 = v[j].z - g1.x, dy1 = v[j].w - g1.y;
            acc0 += fsqrt_approx(fmaf(dx0, dx0, fmaf(dy0, dy0, 1e-12f)));
            acc1 += fsqrt_approx(fmaf(dx1, dx1, fmaf(dy1, dy1, 1e-12f)));
        }
    }
    float acc = acc0 + acc1;
    acc += __shfl_xor_sync(0xffffffffu, acc, 1);
    acc += __shfl_xor_sync(0xffffffffu, acc, 2);

    if (sub == 0 && act)
        g_score[ts_start + tl] = -(acc * 0.02f) * inv_scale;

    // PDL: allow dependent kernel to launch; our g_score store precedes this,
    // so it is visible to the dependent after its griddepcontrol.wait.
    asm volatile("griddepcontrol.launch_dependents;" ::: "memory");
}

// ---------------------------------------------------------------------------
// Kernel B (fused tail, PDL): prefetch all A-independent operands into
// registers, THEN wait on the primary grid, then do g_score reads + CE.
// ---------------------------------------------------------------------------
__global__ __launch_bounds__(512)
void sample_fused_pdl_kernel(const float* __restrict__ traj_scores, // [NT]
                             const float* __restrict__ lane_scores, // [NL]
                             const int*   __restrict__ oracle,      // [NL]
                             const int*   __restrict__ cls_se,      // [B, 2]
                             const int*   __restrict__ trj_se,      // [NL, 2]
                             float* __restrict__ out, int B)
{
    const int b   = blockIdx.x;
    const int tid = threadIdx.x;
    const int wid = tid >> 5;
    const int lid = tid & 31;

    // ---------- prologue: everything independent of kernel A ----------
    const int s = cls_se[2 * b];
    const int e = cls_se[2 * b + 1];
    int nlanes = e - s;
    if (nlanes > 32) nlanes = 32;

    int   ts_st[2];
    int   cntv[2];
    float tA[2], tB[2];
    #pragma unroll
    for (int pass = 0; pass < 2; pass++) {
        const int li = wid + 16 * pass;
        ts_st[pass] = 0; cntv[pass] = 0;
        tA[pass] = -FLT_MAX; tB[pass] = -FLT_MAX;
        if (li < nlanes) {
            const int lane = s + li;
            const int t0 = trj_se[2 * lane];
            const int t1 = trj_se[2 * lane + 1];
            int cnt = t1 - t0;
            if (cnt > 64) cnt = 64;
            ts_st[pass] = t0;
            cntv[pass]  = cnt;
            if (lid < cnt)      tA[pass] = traj_scores[t0 + lid];
            if (lid + 32 < cnt) tB[pass] = traj_scores[t0 + lid + 32];
        }
    }

    float ls = -FLT_MAX;
    int orcv = 0;
    if (wid == 0 && lid < nlanes) {
        ls   = lane_scores[s + lid];
        orcv = oracle[s + lid];
    }

    __shared__ float s_ce[32];
    __shared__ bool  s_last;

    // ---------- wait for primary grid (g_score producer) ----------
    asm volatile("griddepcontrol.wait;" ::: "memory");

    // ---------- per-lane CE (g_score is L2-hot) ----------
    #pragma unroll
    for (int pass = 0; pass < 2; pass++) {
        const int li = wid + 16 * pass;
        if (li < nlanes) {
            const int cnt = cntv[pass];
            const int t0  = ts_st[pass];
            const bool actA = (lid < cnt);
            const bool actB = (lid + 32 < cnt);
            float sA = actA ? g_score[t0 + lid]      : -FLT_MAX;
            float sB = actB ? g_score[t0 + lid + 32] : -FLT_MAX;
            float ce = warp_lane_ce(actA, actB, sA, sB, tA[pass], tB[pass]);
            if (lid == 0) s_ce[li] = ce;
        }
    }
    __syncthreads();

    // ---------- warp 0: sample-level loss ----------
    if (wid == 0) {
        const bool act = (lid < nlanes);
        bool orc = act && (orcv != 0);
        float ce = orc ? s_ce[lid] : 0.0f;

        float m = ls;
        #pragma unroll
        for (int o = 16; o; o >>= 1)
            m = fmaxf(m, __shfl_xor_sync(0xffffffffu, m, o));

        float ev = act ? expf(ls - m) : 0.0f;
        float oc = orc ? 1.0f : 0.0f;
        float Z = ev, OC = oc, CE = ce;
        #pragma unroll
        for (int o = 16; o; o >>= 1) {
            Z  += __shfl_xor_sync(0xffffffffu, Z, o);
            OC += __shfl_xor_sync(0xffffffffu, OC, o);
            CE += __shfl_xor_sync(0xffffffffu, CE, o);
        }
        const float lse = logf(Z);
        float llc = orc ? (m + lse - ls) : 0.0f;
        float LL = llc;
        #pragma unroll
        for (int o = 16; o; o >>= 1)
            LL += __shfl_xor_sync(0xffffffffu, LL, o);

        if (lid == 0)
            g_sample_loss[b] = (LL / OC) * LANE_WEIGHT + CE / OC;
    }

    // ---------- last-block-done: deterministic final mean ----------
    __threadfence();
    __syncthreads();
    if (tid == 0) {
        int t = atomicAdd(&g_done, 1);
        s_last = (t == gridDim.x - 1);
    }
    __syncthreads();
    if (!s_last) return;

    __threadfence();
    __shared__ float red[16];
    float v = 0.0f;
    for (int i = tid; i < B; i += 512) v += g_sample_loss[i];
    #pragma unroll
    for (int o = 16; o; o >>= 1) v += __shfl_xor_sync(0xffffffffu, v, o);
    if (lid == 0) red[wid] = v;
    __syncthreads();
    if (wid == 0) {
        float a = (lid < 16) ? red[lid] : 0.0f;
        #pragma unroll
        for (int o = 8; o; o >>= 1) a += __shfl_xor_sync(0xffffffffu, a, o);
        if (lid == 0) {
            out[0] = a / (float)B;
            *((volatile int*)&g_done) = 0;   // reset for next graph replay
        }
    }
}

// ---------------------------------------------------------------------------
// Generic fallback (any T): block-per-lane ADE + in-block epilogue.
// ---------------------------------------------------------------------------
__global__ __launch_bounds__(256)
void traj_ce_kernel(const float* __restrict__ traj_scores,
                    const float* __restrict__ cand,
                    const float* __restrict__ gt,
                    const float* __restrict__ scales,
                    const int*   __restrict__ cls_se,
                    const int*   __restrict__ trj_se,
                    int B, int T)
{
    const int lane = blockIdx.x;
    const int tid  = threadIdx.x;

    const int ts_start = trj_se[2 * lane];
    const int ts_end   = trj_se[2 * lane + 1];
    int cnt = ts_end - ts_start;
    if (cnt > 64) cnt = 64;

    const int sample = find_sample(cls_se, B, lane);

    __shared__ __align__(8) float s_gt[1024];
    __shared__ float s_score[64], s_ts[64];

    const int t2 = T * 2;
    for (int i = tid; i < t2 && i < 1024; i += blockDim.x)
        s_gt[i] = gt[(size_t)sample * t2 + i];
    __syncthreads();

    const float inv_scale = 1.0f / scales[sample];

    const int q   = tid >> 2;
    const int sub = tid & 3;
    float acc = 0.0f;
    if (q < cnt) {
        const float2* base = reinterpret_cast<const float2*>(cand)
                             + (size_t)(ts_start + q) * T;
        const float2* g2 = reinterpret_cast<const float2*>(s_gt);
        #pragma unroll 4
        for (int t = sub; t < T; t += 4) {
            float2 c = base[t];
            float2 g = g2[t];
            float dx = c.x - g.x;
            float dy = c.y - g.y;
            acc += fsqrt_approx(fmaf(dx, dx, fmaf(dy, dy, 1e-12f)));
        }
    }
    acc += __shfl_xor_sync(0xffffffffu, acc, 1);
    acc += __shfl_xor_sync(0xffffffffu, acc, 2);

    if (sub == 0 && q < cnt) {
        float ade = acc / (float)T;
        s_score[q] = -ade * inv_scale;
        s_ts[q]    = traj_scores[ts_start + q];
    }
    __syncthreads();

    if (tid >= 32) return;
    const bool actA = (tid < cnt);
    const bool actB = (tid + 32 < cnt);
    float sA = actA ? s_score[tid]      : -FLT_MAX;
    float sB = actB ? s_score[tid + 32] : -FLT_MAX;
    float tA = actA ? s_ts[tid]         : -FLT_MAX;
    float tB = actB ? s_ts[tid + 32]    : -FLT_MAX;
    float ce = warp_lane_ce(actA, actB, sA, sB, tA, tB);
    if (tid == 0) g_ce_lane[lane] = ce;
}

__global__ __launch_bounds__(32)
void sample_loss_kernel(const float* __restrict__ lane_scores,
                        const int*   __restrict__ oracle,
                        const int*   __restrict__ cls_se)
{
    const int b = blockIdx.x;
    const int i = threadIdx.x;
    const int s = cls_se[2 * b];
    const int e = cls_se[2 * b + 1];
    int cnt = e - s;
    if (cnt > 32) cnt = 32;

    const bool act = (i < cnt);
    float ls  = act ? lane_scores[s + i] : -FLT_MAX;
    bool  orc = act && (oracle[s + i] != 0);
    float ce  = orc ? g_ce_lane[s + i] : 0.0f;

    float m = ls;
    #pragma unroll
    for (int o = 16; o; o >>= 1) m = fmaxf(m, __shfl_xor_sync(0xffffffffu, m, o));

    float ev = act ? expf(ls - m) : 0.0f;
    float oc = orc ? 1.0f : 0.0f;
    float Z = ev, OC = oc, CE = ce;
    #pragma unroll
    for (int o = 16; o; o >>= 1) {
        Z  += __shfl_xor_sync(0xffffffffu, Z, o);
        OC += __shfl_xor_sync(0xffffffffu, OC, o);
        CE += __shfl_xor_sync(0xffffffffu, CE, o);
    }
    const float lse = logf(Z);
    float llc = orc ? (m + lse - ls) : 0.0f;
    float LL = llc;
    #pragma unroll
    for (int o = 16; o; o >>= 1) LL += __shfl_xor_sync(0xffffffffu, LL, o);

    if (i == 0)
        g_sample_loss[b] = (LL / OC) * LANE_WEIGHT + CE / OC;
}

__global__ __launch_bounds__(256)
void final_mean_kernel(float* __restrict__ out, int B)
{
    __shared__ float red[256];
    const int tid = threadIdx.x;
    float v = 0.0f;
    for (int i = tid; i < B; i += 256) v += g_sample_loss[i];
    red[tid] = v;
    __syncthreads();
    for (int o = 128; o >= 32; o >>= 1) {
        if (tid < o) red[tid] += red[tid + o];
        __syncthreads();
    }
    if (tid < 32) {
        float a = red[tid];
        #pragma unroll
        for (int o = 16; o; o >>= 1) a += __shfl_xor_sync(0xffffffffu, a, o);
        if (tid == 0) out[0] = a / (float)B;
    }
}

// ---------------------------------------------------------------------------
extern "C" void kernel_launch(void* const* d_in, const int* in_sizes, int n_in,
                              void* d_out, int out_size)
{
    const float* lane_scores = (const float*)d_in[0];   // [NL]
    const float* traj_scores = (const float*)d_in[1];   // [NT, 1]
    const float* cand        = (const float*)d_in[2];   // [NT, T, 2]
    const float* gt          = (const float*)d_in[3];   // [B, T, 2]
    const float* scales      = (const float*)d_in[4];   // [B]
    const int*   oracle      = (const int*)  d_in[5];   // [NL]
    const int*   cls_se      = (const int*)  d_in[6];   // [B, 2]
    const int*   trj_se      = (const int*)  d_in[7];   // [NL, 2]

    const int NL = in_sizes[0];
    const int NT = in_sizes[1];
    const int B  = in_sizes[6] / 2;
    const int T  = in_sizes[3] / (2 * B);

    if (T == 50 && NT <= 524288 && B <= 8192) {
        traj_ade_T50_kernel<<<NL, 256>>>(cand, gt, scales, cls_se, trj_se, B);

        // PDL launch: kernel B prefetches independent operands while A drains.
        cudaLaunchConfig_t cfg = {};
        cfg.gridDim  = dim3((unsigned)B, 1, 1);
        cfg.blockDim = dim3(512, 1, 1);
        cfg.dynamicSmemBytes = 0;
        cfg.stream = 0;
        cudaLaunchAttribute attrs[1];
        attrs[0].id = cudaLaunchAttributeProgrammaticStreamSerialization;
        attrs[0].val.programmaticStreamSerializationAllowed = 1;
        cfg.attrs = attrs;
        cfg.numAttrs = 1;
        cudaLaunchKernelEx(&cfg, sample_fused_pdl_kernel,
                           traj_scores, lane_scores, oracle, cls_se, trj_se,
                           (float*)d_out, B);
    } else {
        traj_ce_kernel<<<NL, 256>>>(traj_scores, cand, gt, scales,
                                    cls_se, trj_se, B, T);
        sample_loss_kernel<<<B, 32>>>(lane_scores, oracle, cls_se);
        final_mean_kernel<<<1, 256>>>((float*)d_out, B);
    }
}

// round 16
// speedup vs baseline: 1.2252x; 1.0130x over previous
#include <cuda_runtime.h>
#include <cuda_bf16.h>
#include <float.h>
#include <math.h>
#include <stdint.h>

#define LANE_WEIGHT 1.0f
#define INV_TEMP    10.0f   // 1 / 0.1

// scratch (allocation-free rule: __device__ globals)
__device__ float g_score[524288];       // per-trajectory score, NT <= 524288
__device__ float g_ce_lane[65536];      // ce_per_lane (fallback path)
__device__ float g_sample_loss[8192];   // per-sample loss, B <= 8192
__device__ int   g_done = 0;            // last-block ticket (self-resetting)

__device__ __forceinline__ float fsqrt_approx(float x) {
    float r;
    asm("sqrt.approx.f32 %0, %1;" : "=f"(r) : "f"(x));
    return r;
}

__device__ __forceinline__
int find_sample(const int* __restrict__ cls_se, int B, int lane)
{
    int lo = 0, hi = B - 1;
    while (lo < hi) {
        int mid = (lo + hi + 1) >> 1;
        if (cls_se[2 * mid] <= lane) lo = mid; else hi = mid - 1;
    }
    return lo;
}

// ---------------------------------------------------------------------------
// Per-lane fused softmax CE (two entries per thread, warp-wide shuffles).
// ---------------------------------------------------------------------------
__device__ __forceinline__
float warp_lane_ce(bool actA, bool actB, float sA, float sB, float tA, float tB)
{
    float smax = fmaxf(sA, sB);
    float tmax = fmaxf(tA, tB);
    #pragma unroll
    for (int o = 16; o; o >>= 1) {
        smax = fmaxf(smax, __shfl_xor_sync(0xffffffffu, smax, o));
        tmax = fmaxf(tmax, __shfl_xor_sync(0xffffffffu, tmax, o));
    }
    float pA = actA ? expf((sA - smax) * INV_TEMP) : 0.0f;
    float pB = actB ? expf((sB - smax) * INV_TEMP) : 0.0f;
    float eA = actA ? expf(tA - tmax) : 0.0f;
    float eB = actB ? expf(tB - tmax) : 0.0f;
    float P  = pA + pB;
    float E  = eA + eB;
    float PT = (actA ? pA * tA : 0.0f) + (actB ? pB * tB : 0.0f);
    #pragma unroll
    for (int o = 16; o; o >>= 1) {
        P  += __shfl_xor_sync(0xffffffffu, P,  o);
        E  += __shfl_xor_sync(0xffffffffu, E,  o);
        PT += __shfl_xor_sync(0xffffffffu, PT, o);
    }
    return tmax + logf(E) - PT / P;
}

// ---------------------------------------------------------------------------
// Kernel A (T == 50): bulk-async streaming ADE.
//   One cp.async.bulk (25.6 KB) per block pulls the lane's whole candidate
//   region into smem; the TMA/copy engine keeps DRAM saturated independent of
//   warp scheduling.  Warps overlap the binary search + gt loads with the
//   bulk flight, then compute from smem.  PDL hand-off to kernel B.
// ---------------------------------------------------------------------------
__global__ __launch_bounds__(256)
void traj_ade_T50_bulk_kernel(const float* __restrict__ cand,   // [NT, 50, 2]
                              const float* __restrict__ gt,     // [B, 50, 2]
                              const float* __restrict__ scales, // [B]
                              const int*   __restrict__ cls_se, // [B, 2]
                              const int*   __restrict__ trj_se, // [NL, 2]
                              int B)
{
    const int lane = blockIdx.x;
    const int tid  = threadIdx.x;

    __shared__ __align__(16) float s_cand[6400];   // 64 traj * 50 pts * 2 = 25.6 KB
    __shared__ __align__(8)  uint64_t s_mbar;

    const int ts_start = trj_se[2 * lane];
    const int ts_end   = trj_se[2 * lane + 1];
    int cnt = ts_end - ts_start;
    if (cnt > 64) cnt = 64;
    const int bytes = cnt * 400;                   // 50*2*4 bytes per trajectory

    const uint32_t mbar = (uint32_t)__cvta_generic_to_shared(&s_mbar);
    const uint32_t sdst = (uint32_t)__cvta_generic_to_shared(s_cand);

    if (tid == 0) {
        asm volatile("mbarrier.init.shared.b64 [%0], 1;" :: "r"(mbar) : "memory");
    }
    __syncthreads();

    if (tid == 0) {
        asm volatile("mbarrier.arrive.expect_tx.shared.b64 _, [%0], %1;"
                     :: "r"(mbar), "r"((uint32_t)bytes) : "memory");
        if (bytes > 0) {
            const float* src = cand + (size_t)ts_start * 100;
            asm volatile(
                "cp.async.bulk.shared::cluster.global.mbarrier::complete_tx::bytes "
                "[%0], [%1], %2, [%3];"
                :: "r"(sdst), "l"(src), "r"((uint32_t)bytes), "r"(mbar)
                : "memory");
        }
    }

    // ---- overlap: index math + gt staging while the bulk copy is in flight ----
    const int sample = find_sample(cls_se, B, lane);
    const float inv_scale = 1.0f / scales[sample];
    const float2* gt2 = reinterpret_cast<const float2*>(gt) + sample * 50;

    const int tl  = tid >> 2;          // trajectory within lane (0..63)
    const int sub = tid & 3;
    const bool act = (tl < cnt);

    // preload gt pairs into registers (L1/L2-resident; overlaps bulk flight)
    float2 g0[7], g1[7];
    #pragma unroll
    for (int j = 0; j < 7; j++) {
        const int r = sub + 4 * j;
        if (r < 25) {
            g0[j] = __ldg(&gt2[2 * r]);
            g1[j] = __ldg(&gt2[2 * r + 1]);
        }
    }

    // ---- wait for bulk completion (phase parity 0) ----
    {
        uint32_t done;
        asm volatile(
            "{\n\t.reg .pred p;\n\t"
            "mbarrier.try_wait.parity.shared.b64 p, [%1], 0;\n\t"
            "selp.b32 %0, 1, 0, p;\n\t}"
            : "=r"(done) : "r"(mbar) : "memory");
        while (!done) {
            asm volatile(
                "{\n\t.reg .pred p;\n\t"
                "mbarrier.try_wait.parity.shared.b64 p, [%1], 0;\n\t"
                "selp.b32 %0, 1, 0, p;\n\t}"
                : "=r"(done) : "r"(mbar) : "memory");
        }
    }

    // ---- compute from smem ----
    float acc0 = 0.0f, acc1 = 0.0f;
    if (act) {
        const float4* buf = reinterpret_cast<const float4*>(s_cand) + tl * 25;
        #pragma unroll
        for (int j = 0; j < 7; j++) {
            const int r = sub + 4 * j;
            if (r < 25) {
                float4 v = buf[r];
                float dx0 = v.x - g0[j].x, dy0 = v.y - g0[j].y;
                float dx1 = v.z - g1[j].x, dy1 = v.w - g1[j].y;
                acc0 += fsqrt_approx(fmaf(dx0, dx0, fmaf(dy0, dy0, 1e-12f)));
                acc1 += fsqrt_approx(fmaf(dx1, dx1, fmaf(dy1, dy1, 1e-12f)));
            }
        }
    }
    float acc = acc0 + acc1;
    acc += __shfl_xor_sync(0xffffffffu, acc, 1);
    acc += __shfl_xor_sync(0xffffffffu, acc, 2);

    if (sub == 0 && act)
        g_score[ts_start + tl] = -(acc * 0.02f) * inv_scale;

    // PDL: g_score store precedes this; visible to dependent after its wait.
    asm volatile("griddepcontrol.launch_dependents;" ::: "memory");
}

// ---------------------------------------------------------------------------
// Kernel B (fused tail, PDL — UNCHANGED from the 27.5us R15 config).
// ---------------------------------------------------------------------------
__global__ __launch_bounds__(512)
void sample_fused_pdl_kernel(const float* __restrict__ traj_scores, // [NT]
                             const float* __restrict__ lane_scores, // [NL]
                             const int*   __restrict__ oracle,      // [NL]
                             const int*   __restrict__ cls_se,      // [B, 2]
                             const int*   __restrict__ trj_se,      // [NL, 2]
                             float* __restrict__ out, int B)
{
    const int b   = blockIdx.x;
    const int tid = threadIdx.x;
    const int wid = tid >> 5;
    const int lid = tid & 31;

    // ---------- prologue: everything independent of kernel A ----------
    const int s = cls_se[2 * b];
    const int e = cls_se[2 * b + 1];
    int nlanes = e - s;
    if (nlanes > 32) nlanes = 32;

    int   ts_st[2];
    int   cntv[2];
    float tA[2], tB[2];
    #pragma unroll
    for (int pass = 0; pass < 2; pass++) {
        const int li = wid + 16 * pass;
        ts_st[pass] = 0; cntv[pass] = 0;
        tA[pass] = -FLT_MAX; tB[pass] = -FLT_MAX;
        if (li < nlanes) {
            const int lane = s + li;
            const int t0 = trj_se[2 * lane];
            const int t1 = trj_se[2 * lane + 1];
            int cnt = t1 - t0;
            if (cnt > 64) cnt = 64;
            ts_st[pass] = t0;
            cntv[pass]  = cnt;
            if (lid < cnt)      tA[pass] = traj_scores[t0 + lid];
            if (lid + 32 < cnt) tB[pass] = traj_scores[t0 + lid + 32];
        }
    }

    float ls = -FLT_MAX;
    int orcv = 0;
    if (wid == 0 && lid < nlanes) {
        ls   = lane_scores[s + lid];
        orcv = oracle[s + lid];
    }

    __shared__ float s_ce[32];
    __shared__ bool  s_last;

    // ---------- wait for primary grid (g_score producer) ----------
    asm volatile("griddepcontrol.wait;" ::: "memory");

    // ---------- per-lane CE (g_score is L2-hot) ----------
    #pragma unroll
    for (int pass = 0; pass < 2; pass++) {
        const int li = wid + 16 * pass;
        if (li < nlanes) {
            const int cnt = cntv[pass];
            const int t0  = ts_st[pass];
            const bool actA = (lid < cnt);
            const bool actB = (lid + 32 < cnt);
            float sA = actA ? g_score[t0 + lid]      : -FLT_MAX;
            float sB = actB ? g_score[t0 + lid + 32] : -FLT_MAX;
            float ce = warp_lane_ce(actA, actB, sA, sB, tA[pass], tB[pass]);
            if (lid == 0) s_ce[li] = ce;
        }
    }
    __syncthreads();

    // ---------- warp 0: sample-level loss ----------
    if (wid == 0) {
        const bool act = (lid < nlanes);
        bool orc = act && (orcv != 0);
        float ce = orc ? s_ce[lid] : 0.0f;

        float m = ls;
        #pragma unroll
        for (int o = 16; o; o >>= 1)
            m = fmaxf(m, __shfl_xor_sync(0xffffffffu, m, o));

        float ev = act ? expf(ls - m) : 0.0f;
        float oc = orc ? 1.0f : 0.0f;
        float Z = ev, OC = oc, CE = ce;
        #pragma unroll
        for (int o = 16; o; o >>= 1) {
            Z  += __shfl_xor_sync(0xffffffffu, Z, o);
            OC += __shfl_xor_sync(0xffffffffu, OC, o);
            CE += __shfl_xor_sync(0xffffffffu, CE, o);
        }
        const float lse = logf(Z);
        float llc = orc ? (m + lse - ls) : 0.0f;
        float LL = llc;
        #pragma unroll
        for (int o = 16; o; o >>= 1)
            LL += __shfl_xor_sync(0xffffffffu, LL, o);

        if (lid == 0)
            g_sample_loss[b] = (LL / OC) * LANE_WEIGHT + CE / OC;
    }

    // ---------- last-block-done: deterministic final mean ----------
    __threadfence();
    __syncthreads();
    if (tid == 0) {
        int t = atomicAdd(&g_done, 1);
        s_last = (t == gridDim.x - 1);
    }
    __syncthreads();
    if (!s_last) return;

    __threadfence();
    __shared__ float red[16];
    float v = 0.0f;
    for (int i = tid; i < B; i += 512) v += g_sample_loss[i];
    #pragma unroll
    for (int o = 16; o; o >>= 1) v += __shfl_xor_sync(0xffffffffu, v, o);
    if (lid == 0) red[wid] = v;
    __syncthreads();
    if (wid == 0) {
        float a = (lid < 16) ? red[lid] : 0.0f;
        #pragma unroll
        for (int o = 8; o; o >>= 1) a += __shfl_xor_sync(0xffffffffu, a, o);
        if (lid == 0) {
            out[0] = a / (float)B;
            *((volatile int*)&g_done) = 0;   // reset for next graph replay
        }
    }
}

// ---------------------------------------------------------------------------
// Generic fallback (any T): block-per-lane ADE + in-block epilogue.
// ---------------------------------------------------------------------------
__global__ __launch_bounds__(256)
void traj_ce_kernel(const float* __restrict__ traj_scores,
                    const float* __restrict__ cand,
                    const float* __restrict__ gt,
                    const float* __restrict__ scales,
                    const int*   __restrict__ cls_se,
                    const int*   __restrict__ trj_se,
                    int B, int T)
{
    const int lane = blockIdx.x;
    const int tid  = threadIdx.x;

    const int ts_start = trj_se[2 * lane];
    const int ts_end   = trj_se[2 * lane + 1];
    int cnt = ts_end - ts_start;
    if (cnt > 64) cnt = 64;

    const int sample = find_sample(cls_se, B, lane);

    __shared__ __align__(8) float s_gt[1024];
    __shared__ float s_score[64], s_ts[64];

    const int t2 = T * 2;
    for (int i = tid; i < t2 && i < 1024; i += blockDim.x)
        s_gt[i] = gt[(size_t)sample * t2 + i];
    __syncthreads();

    const float inv_scale = 1.0f / scales[sample];

    const int q   = tid >> 2;
    const int sub = tid & 3;
    float acc = 0.0f;
    if (q < cnt) {
        const float2* base = reinterpret_cast<const float2*>(cand)
                             + (size_t)(ts_start + q) * T;
        const float2* g2 = reinterpret_cast<const float2*>(s_gt);
        #pragma unroll 4
        for (int t = sub; t < T; t += 4) {
            float2 c = base[t];
            float2 g = g2[t];
            float dx = c.x - g.x;
            float dy = c.y - g.y;
            acc += fsqrt_approx(fmaf(dx, dx, fmaf(dy, dy, 1e-12f)));
        }
    }
    acc += __shfl_xor_sync(0xffffffffu, acc, 1);
    acc += __shfl_xor_sync(0xffffffffu, acc, 2);

    if (sub == 0 && q < cnt) {
        float ade = acc / (float)T;
        s_score[q] = -ade * inv_scale;
        s_ts[q]    = traj_scores[ts_start + q];
    }
    __syncthreads();

    if (tid >= 32) return;
    const bool actA = (tid < cnt);
    const bool actB = (tid + 32 < cnt);
    float sA = actA ? s_score[tid]      : -FLT_MAX;
    float sB = actB ? s_score[tid + 32] : -FLT_MAX;
    float tA = actA ? s_ts[tid]         : -FLT_MAX;
    float tB = actB ? s_ts[tid + 32]    : -FLT_MAX;
    float ce = warp_lane_ce(actA, actB, sA, sB, tA, tB);
    if (tid == 0) g_ce_lane[lane] = ce;
}

__global__ __launch_bounds__(32)
void sample_loss_kernel(const float* __restrict__ lane_scores,
                        const int*   __restrict__ oracle,
                        const int*   __restrict__ cls_se)
{
    const int b = blockIdx.x;
    const int i = threadIdx.x;
    const int s = cls_se[2 * b];
    const int e = cls_se[2 * b + 1];
    int cnt = e - s;
    if (cnt > 32) cnt = 32;

    const bool act = (i < cnt);
    float ls  = act ? lane_scores[s + i] : -FLT_MAX;
    bool  orc = act && (oracle[s + i] != 0);
    float ce  = orc ? g_ce_lane[s + i] : 0.0f;

    float m = ls;
    #pragma unroll
    for (int o = 16; o; o >>= 1) m = fmaxf(m, __shfl_xor_sync(0xffffffffu, m, o));

    float ev = act ? expf(ls - m) : 0.0f;
    float oc = orc ? 1.0f : 0.0f;
    float Z = ev, OC = oc, CE = ce;
    #pragma unroll
    for (int o = 16; o; o >>= 1) {
        Z  += __shfl_xor_sync(0xffffffffu, Z, o);
        OC += __shfl_xor_sync(0xffffffffu, OC, o);
        CE += __shfl_xor_sync(0xffffffffu, CE, o);
    }
    const float lse = logf(Z);
    float llc = orc ? (m + lse - ls) : 0.0f;
    float LL = llc;
    #pragma unroll
    for (int o = 16; o; o >>= 1) LL += __shfl_xor_sync(0xffffffffu, LL, o);

    if (i == 0)
        g_sample_loss[b] = (LL / OC) * LANE_WEIGHT + CE / OC;
}

__global__ __launch_bounds__(256)
void final_mean_kernel(float* __restrict__ out, int B)
{
    __shared__ float red[256];
    const int tid = threadIdx.x;
    float v = 0.0f;
    for (int i = tid; i < B; i += 256) v += g_sample_loss[i];
    red[tid] = v;
    __syncthreads();
    for (int o = 128; o >= 32; o >>= 1) {
        if (tid < o) red[tid] += red[tid + o];
        __syncthreads();
    }
    if (tid < 32) {
        float a = red[tid];
        #pragma unroll
        for (int o = 16; o; o >>= 1) a += __shfl_xor_sync(0xffffffffu, a, o);
        if (tid == 0) out[0] = a / (float)B;
    }
}

// ---------------------------------------------------------------------------
extern "C" void kernel_launch(void* const* d_in, const int* in_sizes, int n_in,
                              void* d_out, int out_size)
{
    const float* lane_scores = (const float*)d_in[0];   // [NL]
    const float* traj_scores = (const float*)d_in[1];   // [NT, 1]
    const float* cand        = (const float*)d_in[2];   // [NT, T, 2]
    const float* gt          = (const float*)d_in[3];   // [B, T, 2]
    const float* scales      = (const float*)d_in[4];   // [B]
    const int*   oracle      = (const int*)  d_in[5];   // [NL]
    const int*   cls_se      = (const int*)  d_in[6];   // [B, 2]
    const int*   trj_se      = (const int*)  d_in[7];   // [NL, 2]

    const int NL = in_sizes[0];
    const int NT = in_sizes[1];
    const int B  = in_sizes[6] / 2;
    const int T  = in_sizes[3] / (2 * B);

    if (T == 50 && NT <= 524288 && B <= 8192) {
        traj_ade_T50_bulk_kernel<<<NL, 256>>>(cand, gt, scales, cls_se,
                                              trj_se, B);

        // PDL launch: kernel B prefetches independent operands while A drains.
        cudaLaunchConfig_t cfg = {};
        cfg.gridDim  = dim3((unsigned)B, 1, 1);
        cfg.blockDim = dim3(512, 1, 1);
        cfg.dynamicSmemBytes = 0;
        cfg.stream = 0;
        cudaLaunchAttribute attrs[1];
        attrs[0].id = cudaLaunchAttributeProgrammaticStreamSerialization;
        attrs[0].val.programmaticStreamSerializationAllowed = 1;
        cfg.attrs = attrs;
        cfg.numAttrs = 1;
        cudaLaunchKernelEx(&cfg, sample_fused_pdl_kernel,
                           traj_scores, lane_scores, oracle, cls_se, trj_se,
                           (float*)d_out, B);
    } else {
        traj_ce_kernel<<<NL, 256>>>(traj_scores, cand, gt, scales,
                                    cls_se, trj_se, B, T);
        sample_loss_kernel<<<B, 32>>>(lane_scores, oracle, cls_se);
        final_mean_kernel<<<1, 256>>>((float*)d_out, B);
    }
}